// round 11
// baseline (speedup 1.0000x reference)
#include <cuda_runtime.h>
#include <cuda_bf16.h>
#include <math.h>
#include <stdint.h>

#define BB 2
#define NN 2048
#define CC 1024
#define HH 16
#define DD 64
#define MR (BB*NN)          // 4096 rows
#define QK_SCALE 0.125f     // 64^-0.5

// ---- global scratch (allocation-free rule) --------------------------------
__device__ float g_qkv[(size_t)MR * 3 * CC];                  // fp32 qkv
__device__ __nv_bfloat16 g_xh[(size_t)MR * CC],  g_xl[(size_t)MR * CC];
__device__ __nv_bfloat16 g_wqh[(size_t)3 * CC * CC], g_wql[(size_t)3 * CC * CC];
__device__ __nv_bfloat16 g_wph[(size_t)CC * CC], g_wpl[(size_t)CC * CC];
__device__ __nv_bfloat16 g_ah[(size_t)MR * CC],  g_al[(size_t)MR * CC];
// RoPE'd, split, head-contiguous [b][h][n][64]
__device__ __nv_bfloat16 g_Qh[(size_t)MR * CC], g_Ql[(size_t)MR * CC];
__device__ __nv_bfloat16 g_Kh[(size_t)MR * CC], g_Kl[(size_t)MR * CC];
__device__ __nv_bfloat16 g_Vh[(size_t)MR * CC], g_Vl[(size_t)MR * CC];

// ---- helpers --------------------------------------------------------------
__device__ __forceinline__ uint32_t smem_u32(const void* p) {
    return (uint32_t)__cvta_generic_to_shared(p);
}
__device__ __forceinline__ void cp16(uint32_t dst, const void* src) {
    asm volatile("cp.async.cg.shared.global [%0], [%1], 16;"
                 :: "r"(dst), "l"(src) : "memory");
}
__device__ __forceinline__ void cp_commit() {
    asm volatile("cp.async.commit_group;" ::: "memory");
}
__device__ __forceinline__ void cp_wait1() {
    asm volatile("cp.async.wait_group 1;" ::: "memory");
}
__device__ __forceinline__ void ldmx4(uint32_t* r, uint32_t addr) {
    asm volatile("ldmatrix.sync.aligned.m8n8.x4.shared.b16 {%0,%1,%2,%3}, [%4];"
                 : "=r"(r[0]), "=r"(r[1]), "=r"(r[2]), "=r"(r[3]) : "r"(addr));
}
__device__ __forceinline__ void ldmx4t(uint32_t* r, uint32_t addr) {
    asm volatile("ldmatrix.sync.aligned.m8n8.x4.trans.shared.b16 {%0,%1,%2,%3}, [%4];"
                 : "=r"(r[0]), "=r"(r[1]), "=r"(r[2]), "=r"(r[3]) : "r"(addr));
}
__device__ __forceinline__ void mma_bf16(float* c, const uint32_t* a, const uint32_t* b) {
    asm volatile(
        "mma.sync.aligned.m16n8k16.row.col.f32.bf16.bf16.f32 "
        "{%0,%1,%2,%3}, {%4,%5,%6,%7}, {%8,%9}, {%0,%1,%2,%3};"
        : "+f"(c[0]), "+f"(c[1]), "+f"(c[2]), "+f"(c[3])
        : "r"(a[0]), "r"(a[1]), "r"(a[2]), "r"(a[3]), "r"(b[0]), "r"(b[1]));
}
__device__ __forceinline__ uint32_t pack2bf(float x, float y) {
    __nv_bfloat162 h = __floats2bfloat162_rn(x, y);
    return *(uint32_t*)&h;
}
__device__ __forceinline__ void split2(float x, float y, uint32_t& hi, uint32_t& lo) {
    float hx = __bfloat162float(__float2bfloat16(x));
    float hy = __bfloat162float(__float2bfloat16(y));
    hi = pack2bf(hx, hy);
    lo = pack2bf(x - hx, y - hy);
}

// ---------------------------------------------------------------------------
// merged split: x | w_qkv | w_proj  fp32 -> hi/lo bf16 in ONE launch
// ---------------------------------------------------------------------------
#define N4_X   (MR * CC / 4)             // 1048576
#define N4_WQ  (3 * CC * CC / 4)         // 786432
#define N4_WP  (CC * CC / 4)             // 262144
#define N4_ALL (N4_X + N4_WQ + N4_WP)

__global__ void split_all(const float* __restrict__ x,
                          const float* __restrict__ wq,
                          const float* __restrict__ wp) {
    int i = blockIdx.x * blockDim.x + threadIdx.x;
    if (i >= N4_ALL) return;
    const float* src;
    __nv_bfloat16 *hi, *lo;
    int j;
    if (i < N4_X) {
        src = x; hi = g_xh; lo = g_xl; j = i;
    } else if (i < N4_X + N4_WQ) {
        src = wq; hi = g_wqh; lo = g_wql; j = i - N4_X;
    } else {
        src = wp; hi = g_wph; lo = g_wpl; j = i - N4_X - N4_WQ;
    }
    float4 v = ((const float4*)src)[j];
    uint32_t h0, l0, h1, l1;
    split2(v.x, v.y, h0, l0);
    split2(v.z, v.w, h1, l1);
    ((uint2*)hi)[j] = make_uint2(h0, h1);
    ((uint2*)lo)[j] = make_uint2(l0, l1);
}

// ---------------------------------------------------------------------------
// prep: RoPE q/k (+scale q), split q/k/v into [b][h][n][64]
// ---------------------------------------------------------------------------
__global__ void prep_qkv(const float* __restrict__ qkv,
                         const float* __restrict__ freqs) {
    int gid = blockIdx.x * blockDim.x + threadIdx.x;
    int half = gid & 1;
    int h = (gid >> 1) & (HH - 1);
    int n = (gid >> 5) & (NN - 1);
    int b = gid >> 16;

    const float* base = qkv + (size_t)(b * NN + n) * 3 * CC + h * DD + half * 32;
    const float* fp = freqs + (size_t)n * 32 + half * 16;
    size_t orow = ((size_t)(b * HH + h) * NN + n) * 64 + half * 32;

#pragma unroll
    for (int j = 0; j < 32; j += 4) {
        float c0, s0, c1, s1;
        __sincosf(fp[j / 2], &s0, &c0);
        __sincosf(fp[j / 2 + 1], &s1, &c1);
        uint32_t hi0, lo0, hi1, lo1;

        float4 q = *(const float4*)(base + j);
        split2((q.x * c0 - q.y * s0) * QK_SCALE, (q.x * s0 + q.y * c0) * QK_SCALE, hi0, lo0);
        split2((q.z * c1 - q.w * s1) * QK_SCALE, (q.z * s1 + q.w * c1) * QK_SCALE, hi1, lo1);
        *(uint2*)(g_Qh + orow + j) = make_uint2(hi0, hi1);
        *(uint2*)(g_Ql + orow + j) = make_uint2(lo0, lo1);

        float4 k = *(const float4*)(base + CC + j);
        split2(k.x * c0 - k.y * s0, k.x * s0 + k.y * c0, hi0, lo0);
        split2(k.z * c1 - k.w * s1, k.z * s1 + k.w * c1, hi1, lo1);
        *(uint2*)(g_Kh + orow + j) = make_uint2(hi0, hi1);
        *(uint2*)(g_Kl + orow + j) = make_uint2(lo0, lo1);

        float4 v = *(const float4*)(base + 2 * CC + j);
        split2(v.x, v.y, hi0, lo0);
        split2(v.z, v.w, hi1, lo1);
        *(uint2*)(g_Vh + orow + j) = make_uint2(hi0, hi1);
        *(uint2*)(g_Vl + orow + j) = make_uint2(lo0, lo1);
    }
}

// ---------------------------------------------------------------------------
// GEMM (round-7 proven config, .cg staging): CTA 128x128, K-chunk 32,
// 8 warps (64x32 warp tile), cp.async double-buffered, 2 CTAs/SM.
// ---------------------------------------------------------------------------
#define SPAD 40
#define G_ARR (128 * SPAD * 2)      // 10240 B per array
#define G_STAGE (4 * G_ARR)         // 40960 B per stage

__global__ __launch_bounds__(256, 2) void gemm_b16(
        const __nv_bfloat16* __restrict__ Ahg, const __nv_bfloat16* __restrict__ Alg,
        const __nv_bfloat16* __restrict__ Whg, const __nv_bfloat16* __restrict__ Wlg,
        const float* __restrict__ bias, float* __restrict__ Cm,
        int M, int Nc, int K) {
    extern __shared__ __align__(16) char sm[];
    const uint32_t sbase = smem_u32(sm);

    const int tid = threadIdx.x;
    const int wid = tid >> 5;
    const int lane = tid & 31;
    const int m0 = blockIdx.y * 128;
    const int n0 = blockIdx.x * 128;
    const int wm = (wid >> 2) * 64;
    const int wn = (wid & 3) * 32;

    const int lrow = tid >> 1;
    const int lcol = (tid & 1) * 16;
    const __nv_bfloat16* Ahp = Ahg + (size_t)(m0 + lrow) * K + lcol;
    const __nv_bfloat16* Alp = Alg + (size_t)(m0 + lrow) * K + lcol;
    const __nv_bfloat16* Whp = Whg + (size_t)(n0 + lrow) * K + lcol;
    const __nv_bfloat16* Wlp = Wlg + (size_t)(n0 + lrow) * K + lcol;
    const uint32_t ldst = sbase + (lrow * SPAD + lcol) * 2;

    float acc[4][4][4];
#pragma unroll
    for (int i = 0; i < 4; i++)
#pragma unroll
        for (int j = 0; j < 4; j++)
#pragma unroll
            for (int f = 0; f < 4; f++) acc[i][j][f] = 0.f;

    const uint32_t a_row = wm + (lane & 15);
    const uint32_t a_coff = (lane >> 4) * 8;
    const uint32_t b_row = wn + ((lane >> 4) << 3) + (lane & 7);
    const uint32_t b_coff = ((lane >> 3) & 1) * 8;

    {
        uint32_t d = ldst;
        cp16(d, Ahp); cp16(d + 16, Ahp + 8);
        cp16(d + G_ARR, Alp); cp16(d + G_ARR + 16, Alp + 8);
        cp16(d + 2 * G_ARR, Whp); cp16(d + 2 * G_ARR + 16, Whp + 8);
        cp16(d + 3 * G_ARR, Wlp); cp16(d + 3 * G_ARR + 16, Wlp + 8);
    }
    cp_commit();

    int buf = 0;
    for (int k0 = 0; k0 < K; k0 += 32) {
        if (k0 + 32 < K) {
            uint32_t d = ldst + (buf ^ 1) * G_STAGE;
            int kn = k0 + 32;
            cp16(d, Ahp + kn); cp16(d + 16, Ahp + kn + 8);
            cp16(d + G_ARR, Alp + kn); cp16(d + G_ARR + 16, Alp + kn + 8);
            cp16(d + 2 * G_ARR, Whp + kn); cp16(d + 2 * G_ARR + 16, Whp + kn + 8);
            cp16(d + 3 * G_ARR, Wlp + kn); cp16(d + 3 * G_ARR + 16, Wlp + kn + 8);
        }
        cp_commit();
        cp_wait1();
        __syncthreads();

        const uint32_t sAh = sbase + buf * G_STAGE;
        const uint32_t sAl = sAh + G_ARR;
        const uint32_t sBh = sAh + 2 * G_ARR;
        const uint32_t sBl = sAh + 3 * G_ARR;

#pragma unroll
        for (int ks = 0; ks < 2; ks++) {
            const uint32_t kc = ks * 16;
            uint32_t afh[4][4], afl[4][4];
#pragma unroll
            for (int mt = 0; mt < 4; mt++) {
                uint32_t off = ((a_row + mt * 16) * SPAD + kc + a_coff) * 2;
                ldmx4(afh[mt], sAh + off);
                ldmx4(afl[mt], sAl + off);
            }
            uint32_t bfh[2][4], bfl[2][4];
#pragma unroll
            for (int bt = 0; bt < 2; bt++) {
                uint32_t off = ((b_row + bt * 16) * SPAD + kc + b_coff) * 2;
                ldmx4(bfh[bt], sBh + off);
                ldmx4(bfl[bt], sBl + off);
            }
#pragma unroll
            for (int mt = 0; mt < 4; mt++)
#pragma unroll
                for (int nt = 0; nt < 4; nt++) {
                    uint32_t* bh = &bfh[nt >> 1][(nt & 1) * 2];
                    uint32_t* bl = &bfl[nt >> 1][(nt & 1) * 2];
                    mma_bf16(acc[mt][nt], afh[mt], bh);
                    mma_bf16(acc[mt][nt], afh[mt], bl);
                    mma_bf16(acc[mt][nt], afl[mt], bh);
                }
        }
        __syncthreads();
        buf ^= 1;
    }

    const int erow = lane >> 2;
    const int ecol = (lane & 3) * 2;
#pragma unroll
    for (int mt = 0; mt < 4; mt++) {
#pragma unroll
        for (int nt = 0; nt < 4; nt++) {
            int gr = m0 + wm + mt * 16 + erow;
            int gc = n0 + wn + nt * 8 + ecol;
            float b0 = 0.f, b1 = 0.f;
            if (bias) { b0 = bias[gc]; b1 = bias[gc + 1]; }
            *(float2*)(Cm + (size_t)gr * Nc + gc) =
                make_float2(acc[mt][nt][0] + b0, acc[mt][nt][1] + b1);
            *(float2*)(Cm + (size_t)(gr + 8) * Nc + gc) =
                make_float2(acc[mt][nt][2] + b0, acc[mt][nt][3] + b1);
        }
    }
}

// ---------------------------------------------------------------------------
// Flash attention (round-7 proven config, .cg): 128 q-rows, 256 threads,
// 8 warps, cp.async double-buffered K/V. smem: 36864 + 2 x 36864 = 110592 B.
// ---------------------------------------------------------------------------
#define APAD 72
#define A_QARR (128 * APAD * 2)       // 18432 B (Qh or Ql)
#define A_KARR (64 * APAD * 2)        // 9216 B per KV array
#define A_KSTAGE (4 * A_KARR)         // 36864 B per stage
#define A_KBASE (2 * A_QARR)          // 36864

__global__ __launch_bounds__(256, 1) void attn_mma(void) {
    extern __shared__ __align__(16) char sm[];
    const uint32_t sbase = smem_u32(sm);

    const int t = threadIdx.x;
    const int wid = t >> 5;
    const int lane = t & 31;
    const int h = blockIdx.y;
    const int b = blockIdx.z;
    const int q0 = blockIdx.x * 128;

    const size_t hbase = (size_t)(b * HH + h) * NN * 64;

    const int krow = t >> 2, kc16 = (t & 3) * 16;
    const uint32_t kdst = sbase + A_KBASE + (krow * APAD + kc16) * 2;
    const size_t ksrc0 = hbase + (size_t)krow * 64 + kc16;

    {
        uint32_t d = kdst;
        cp16(d, g_Kh + ksrc0); cp16(d + 16, g_Kh + ksrc0 + 8);
        cp16(d + A_KARR, g_Kl + ksrc0); cp16(d + A_KARR + 16, g_Kl + ksrc0 + 8);
        cp16(d + 2 * A_KARR, g_Vh + ksrc0); cp16(d + 2 * A_KARR + 16, g_Vh + ksrc0 + 8);
        cp16(d + 3 * A_KARR, g_Vl + ksrc0); cp16(d + 3 * A_KARR + 16, g_Vl + ksrc0 + 8);
    }
    cp_commit();

    __nv_bfloat16* const Qh = (__nv_bfloat16*)sm;
    __nv_bfloat16* const Ql = Qh + 128 * APAD;
    {
        int row = t >> 1, half = (t & 1) * 32;
        size_t src = hbase + (size_t)(q0 + row) * 64 + half;
        size_t dst = (size_t)row * APAD + half;
#pragma unroll
        for (int j = 0; j < 32; j += 8) {
            *(uint4*)(Qh + dst + j) = *(const uint4*)(g_Qh + src + j);
            *(uint4*)(Ql + dst + j) = *(const uint4*)(g_Ql + src + j);
        }
    }
    __syncthreads();

    uint32_t qfh[4][4], qfl[4][4];
    {
        const uint32_t arow = wid * 16 + (lane & 15);
        const uint32_t acoff = (lane >> 4) * 8;
#pragma unroll
        for (int ks = 0; ks < 4; ks++) {
            uint32_t off = (arow * APAD + ks * 16 + acoff) * 2;
            ldmx4(qfh[ks], sbase + off);
            ldmx4(qfl[ks], sbase + A_QARR + off);
        }
    }

    float o[8][4];
#pragma unroll
    for (int i = 0; i < 8; i++)
#pragma unroll
        for (int f = 0; f < 4; f++) o[i][f] = 0.f;
    float m0 = -1e30f, m1 = -1e30f, l0 = 0.f, l1 = 0.f;

    const uint32_t b_row = ((lane >> 4) << 3) + (lane & 7);
    const uint32_t b_coff = ((lane >> 3) & 1) * 8;
    const uint32_t v_row = ((lane >> 3) & 1) * 8 + (lane & 7);
    const uint32_t v_coff = (lane >> 4) * 8;

    int buf = 0;
    for (int kt = 0; kt < NN / 64; kt++) {
        if (kt + 1 < NN / 64) {
            uint32_t d = kdst + (buf ^ 1) * A_KSTAGE;
            size_t src = ksrc0 + (size_t)(kt + 1) * 64 * 64;
            cp16(d, g_Kh + src); cp16(d + 16, g_Kh + src + 8);
            cp16(d + A_KARR, g_Kl + src); cp16(d + A_KARR + 16, g_Kl + src + 8);
            cp16(d + 2 * A_KARR, g_Vh + src); cp16(d + 2 * A_KARR + 16, g_Vh + src + 8);
            cp16(d + 3 * A_KARR, g_Vl + src); cp16(d + 3 * A_KARR + 16, g_Vl + src + 8);
        }
        cp_commit();
        cp_wait1();
        __syncthreads();

        const uint32_t sKh = sbase + A_KBASE + buf * A_KSTAGE;
        const uint32_t sKl = sKh + A_KARR;
        const uint32_t sVh = sKh + 2 * A_KARR;
        const uint32_t sVl = sKh + 3 * A_KARR;

        float s[8][4];
#pragma unroll
        for (int i = 0; i < 8; i++)
#pragma unroll
            for (int f = 0; f < 4; f++) s[i][f] = 0.f;
#pragma unroll
        for (int ks = 0; ks < 4; ks++) {
            const uint32_t kc = ks * 16;
#pragma unroll
            for (int g = 0; g < 4; g++) {
                uint32_t bh[4], bl[4];
                uint32_t off = ((g * 16 + b_row) * APAD + kc + b_coff) * 2;
                ldmx4(bh, sKh + off);
                ldmx4(bl, sKl + off);
                mma_bf16(s[2 * g],     qfh[ks], &bh[0]);
                mma_bf16(s[2 * g],     qfh[ks], &bl[0]);
                mma_bf16(s[2 * g],     qfl[ks], &bh[0]);
                mma_bf16(s[2 * g + 1], qfh[ks], &bh[2]);
                mma_bf16(s[2 * g + 1], qfh[ks], &bl[2]);
                mma_bf16(s[2 * g + 1], qfl[ks], &bh[2]);
            }
        }

        float tm0 = -1e30f, tm1 = -1e30f;
#pragma unroll
        for (int nt = 0; nt < 8; nt++) {
            tm0 = fmaxf(tm0, fmaxf(s[nt][0], s[nt][1]));
            tm1 = fmaxf(tm1, fmaxf(s[nt][2], s[nt][3]));
        }
        tm0 = fmaxf(tm0, __shfl_xor_sync(0xffffffffu, tm0, 1));
        tm0 = fmaxf(tm0, __shfl_xor_sync(0xffffffffu, tm0, 2));
        tm1 = fmaxf(tm1, __shfl_xor_sync(0xffffffffu, tm1, 1));
        tm1 = fmaxf(tm1, __shfl_xor_sync(0xffffffffu, tm1, 2));
        float mn0 = fmaxf(m0, tm0), mn1 = fmaxf(m1, tm1);
        float al0 = __expf(m0 - mn0), al1 = __expf(m1 - mn1);
        m0 = mn0; m1 = mn1;
        float rs0 = 0.f, rs1 = 0.f;
#pragma unroll
        for (int nt = 0; nt < 8; nt++) {
            s[nt][0] = __expf(s[nt][0] - m0);
            s[nt][1] = __expf(s[nt][1] - m0);
            s[nt][2] = __expf(s[nt][2] - m1);
            s[nt][3] = __expf(s[nt][3] - m1);
            rs0 += s[nt][0] + s[nt][1];
            rs1 += s[nt][2] + s[nt][3];
        }
        rs0 += __shfl_xor_sync(0xffffffffu, rs0, 1);
        rs0 += __shfl_xor_sync(0xffffffffu, rs0, 2);
        rs1 += __shfl_xor_sync(0xffffffffu, rs1, 1);
        rs1 += __shfl_xor_sync(0xffffffffu, rs1, 2);
        l0 = l0 * al0 + rs0;
        l1 = l1 * al1 + rs1;
#pragma unroll
        for (int nt = 0; nt < 8; nt++) {
            o[nt][0] *= al0; o[nt][1] *= al0;
            o[nt][2] *= al1; o[nt][3] *= al1;
        }

        uint32_t ph[4][4], pl[4][4];
#pragma unroll
        for (int ks = 0; ks < 4; ks++) {
#pragma unroll
            for (int hf = 0; hf < 2; hf++) {
                int nt = 2 * ks + hf;
                split2(s[nt][0], s[nt][1], ph[ks][hf * 2 + 0], pl[ks][hf * 2 + 0]);
                split2(s[nt][2], s[nt][3], ph[ks][hf * 2 + 1], pl[ks][hf * 2 + 1]);
            }
        }

#pragma unroll
        for (int ks = 0; ks < 4; ks++) {
            const uint32_t kr = ks * 16 + v_row;
#pragma unroll
            for (int g = 0; g < 4; g++) {
                uint32_t vh4[4], vl4[4];
                uint32_t off = (kr * APAD + g * 16 + v_coff) * 2;
                ldmx4t(vh4, sVh + off);
                ldmx4t(vl4, sVl + off);
                mma_bf16(o[2 * g],     ph[ks], &vh4[0]);
                mma_bf16(o[2 * g],     ph[ks], &vl4[0]);
                mma_bf16(o[2 * g],     pl[ks], &vh4[0]);
                mma_bf16(o[2 * g + 1], ph[ks], &vh4[2]);
                mma_bf16(o[2 * g + 1], ph[ks], &vl4[2]);
                mma_bf16(o[2 * g + 1], pl[ks], &vh4[2]);
            }
        }
        __syncthreads();
        buf ^= 1;
    }

    float inv0 = 1.f / l0, inv1 = 1.f / l1;
    int r0 = q0 + wid * 16 + (lane >> 2);
    int cbase = (lane & 3) * 2;
    size_t base0 = (size_t)(b * NN + r0) * CC + h * DD + cbase;
    size_t base1 = base0 + (size_t)8 * CC;
#pragma unroll
    for (int nt = 0; nt < 8; nt++) {
        uint32_t hi, lo;
        split2(o[nt][0] * inv0, o[nt][1] * inv0, hi, lo);
        *(uint32_t*)(g_ah + base0 + nt * 8) = hi;
        *(uint32_t*)(g_al + base0 + nt * 8) = lo;
        split2(o[nt][2] * inv1, o[nt][3] * inv1, hi, lo);
        *(uint32_t*)(g_ah + base1 + nt * 8) = hi;
        *(uint32_t*)(g_al + base1 + nt * 8) = lo;
    }
}

// ---------------------------------------------------------------------------
extern "C" void kernel_launch(void* const* d_in, const int* in_sizes, int n_in,
                              void* d_out, int out_size) {
    const float* x      = (const float*)d_in[0];
    const float* freqs  = (const float*)d_in[1];
    const float* w_qkv  = (const float*)d_in[2];
    const float* w_proj = (const float*)d_in[3];
    const float* b_proj = (const float*)d_in[4];
    float* out = (float*)d_out;

    float* qkv;
    cudaGetSymbolAddress((void**)&qkv, g_qkv);
    __nv_bfloat16 *xh, *xl, *wqh, *wql, *wph, *wpl, *ah, *al;
    cudaGetSymbolAddress((void**)&xh, g_xh);
    cudaGetSymbolAddress((void**)&xl, g_xl);
    cudaGetSymbolAddress((void**)&wqh, g_wqh);
    cudaGetSymbolAddress((void**)&wql, g_wql);
    cudaGetSymbolAddress((void**)&wph, g_wph);
    cudaGetSymbolAddress((void**)&wpl, g_wpl);
    cudaGetSymbolAddress((void**)&ah, g_ah);
    cudaGetSymbolAddress((void**)&al, g_al);

    static int smem_set = 0;
    if (!smem_set) {
        cudaFuncSetAttribute(gemm_b16, cudaFuncAttributeMaxDynamicSharedMemorySize,
                             2 * G_STAGE);
        cudaFuncSetAttribute(attn_mma, cudaFuncAttributeMaxDynamicSharedMemorySize,
                             A_KBASE + 2 * A_KSTAGE);
        smem_set = 1;
    }

    // 0) pre-split all fp32 inputs (single launch)
    split_all<<<(N4_ALL + 255) / 256, 256>>>(x, w_qkv, w_proj);

    // 1) qkv = x @ w_qkv^T
    gemm_b16<<<dim3(3 * CC / 128, MR / 128), 256, 2 * G_STAGE>>>(
        xh, xl, wqh, wql, nullptr, qkv, MR, 3 * CC, CC);
    // 2) RoPE + split q/k/v (head-contiguous)
    prep_qkv<<<(BB * NN * HH * 2) / 256, 256>>>(qkv, freqs);
    // 3) attention (outputs pre-split g_ah/g_al)
    attn_mma<<<dim3(NN / 128, HH, BB), 256, A_KBASE + 2 * A_KSTAGE>>>();
    // 4) out = attn @ w_proj^T + b_proj
    gemm_b16<<<dim3(CC / 128, MR / 128), 256, 2 * G_STAGE>>>(
        ah, al, wph, wpl, b_proj, out, MR, CC, CC);
}

// round 12
// speedup vs baseline: 1.0647x; 1.0647x over previous
#include <cuda_runtime.h>
#include <cuda_bf16.h>
#include <math.h>
#include <stdint.h>

#define BB 2
#define NN 2048
#define CC 1024
#define HH 16
#define DD 64
#define MR (BB*NN)          // 4096 rows
#define QK_SCALE 0.125f     // 64^-0.5
#define LOG2E 1.4426950408889634f

// ---- global scratch (allocation-free rule) --------------------------------
__device__ float g_qkv[(size_t)MR * 3 * CC];                  // fp32 qkv
__device__ __nv_bfloat16 g_xh[(size_t)MR * CC],  g_xl[(size_t)MR * CC];
__device__ __nv_bfloat16 g_wqh[(size_t)3 * CC * CC], g_wql[(size_t)3 * CC * CC];
__device__ __nv_bfloat16 g_wph[(size_t)CC * CC], g_wpl[(size_t)CC * CC];
__device__ __nv_bfloat16 g_ah[(size_t)MR * CC],  g_al[(size_t)MR * CC];
// RoPE'd, split, head-contiguous [b][h][n][64]; Q pre-scaled by SCALE*log2e
__device__ __nv_bfloat16 g_Qh[(size_t)MR * CC], g_Ql[(size_t)MR * CC];
__device__ __nv_bfloat16 g_Kh[(size_t)MR * CC], g_Kl[(size_t)MR * CC];
__device__ __nv_bfloat16 g_Vh[(size_t)MR * CC], g_Vl[(size_t)MR * CC];

// ---- helpers --------------------------------------------------------------
__device__ __forceinline__ uint32_t smem_u32(const void* p) {
    return (uint32_t)__cvta_generic_to_shared(p);
}
__device__ __forceinline__ void cp16(uint32_t dst, const void* src) {
    asm volatile("cp.async.ca.shared.global [%0], [%1], 16;"
                 :: "r"(dst), "l"(src) : "memory");
}
__device__ __forceinline__ void cp_commit() {
    asm volatile("cp.async.commit_group;" ::: "memory");
}
__device__ __forceinline__ void cp_wait1() {
    asm volatile("cp.async.wait_group 1;" ::: "memory");
}
__device__ __forceinline__ void ldmx4(uint32_t* r, uint32_t addr) {
    asm volatile("ldmatrix.sync.aligned.m8n8.x4.shared.b16 {%0,%1,%2,%3}, [%4];"
                 : "=r"(r[0]), "=r"(r[1]), "=r"(r[2]), "=r"(r[3]) : "r"(addr));
}
__device__ __forceinline__ void ldmx4t(uint32_t* r, uint32_t addr) {
    asm volatile("ldmatrix.sync.aligned.m8n8.x4.trans.shared.b16 {%0,%1,%2,%3}, [%4];"
                 : "=r"(r[0]), "=r"(r[1]), "=r"(r[2]), "=r"(r[3]) : "r"(addr));
}
__device__ __forceinline__ void mma_bf16(float* c, const uint32_t* a, const uint32_t* b) {
    asm volatile(
        "mma.sync.aligned.m16n8k16.row.col.f32.bf16.bf16.f32 "
        "{%0,%1,%2,%3}, {%4,%5,%6,%7}, {%8,%9}, {%0,%1,%2,%3};"
        : "+f"(c[0]), "+f"(c[1]), "+f"(c[2]), "+f"(c[3])
        : "r"(a[0]), "r"(a[1]), "r"(a[2]), "r"(a[3]), "r"(b[0]), "r"(b[1]));
}
__device__ __forceinline__ uint32_t pack2bf(float x, float y) {
    __nv_bfloat162 h = __floats2bfloat162_rn(x, y);
    return *(uint32_t*)&h;
}
__device__ __forceinline__ void split2(float x, float y, uint32_t& hi, uint32_t& lo) {
    float hx = __bfloat162float(__float2bfloat16(x));
    float hy = __bfloat162float(__float2bfloat16(y));
    hi = pack2bf(hx, hy);
    lo = pack2bf(x - hx, y - hy);
}

// ---------------------------------------------------------------------------
// split fp32 -> hi/lo bf16 (vectorized by 4)
// ---------------------------------------------------------------------------
__global__ void split_kernel(const float* __restrict__ src,
                             __nv_bfloat16* __restrict__ hi,
                             __nv_bfloat16* __restrict__ lo, int n4) {
    int i = blockIdx.x * blockDim.x + threadIdx.x;
    if (i >= n4) return;
    float4 v = ((const float4*)src)[i];
    uint32_t h0, l0, h1, l1;
    split2(v.x, v.y, h0, l0);
    split2(v.z, v.w, h1, l1);
    ((uint2*)hi)[i] = make_uint2(h0, h1);
    ((uint2*)lo)[i] = make_uint2(l0, l1);
}

// ---------------------------------------------------------------------------
// prep: RoPE q/k, q scaled by QK_SCALE*log2e (exp2 softmax domain),
// split q/k/v into [b][h][n][64]
// ---------------------------------------------------------------------------
__global__ void prep_qkv(const float* __restrict__ qkv,
                         const float* __restrict__ freqs) {
    int gid = blockIdx.x * blockDim.x + threadIdx.x;
    int half = gid & 1;
    int h = (gid >> 1) & (HH - 1);
    int n = (gid >> 5) & (NN - 1);
    int b = gid >> 16;

    const float* base = qkv + (size_t)(b * NN + n) * 3 * CC + h * DD + half * 32;
    const float* fp = freqs + (size_t)n * 32 + half * 16;
    size_t orow = ((size_t)(b * HH + h) * NN + n) * 64 + half * 32;
    const float QS = QK_SCALE * LOG2E;

#pragma unroll
    for (int j = 0; j < 32; j += 4) {
        float c0, s0, c1, s1;
        __sincosf(fp[j / 2], &s0, &c0);
        __sincosf(fp[j / 2 + 1], &s1, &c1);
        uint32_t hi0, lo0, hi1, lo1;

        float4 q = *(const float4*)(base + j);
        split2((q.x * c0 - q.y * s0) * QS, (q.x * s0 + q.y * c0) * QS, hi0, lo0);
        split2((q.z * c1 - q.w * s1) * QS, (q.z * s1 + q.w * c1) * QS, hi1, lo1);
        *(uint2*)(g_Qh + orow + j) = make_uint2(hi0, hi1);
        *(uint2*)(g_Ql + orow + j) = make_uint2(lo0, lo1);

        float4 k = *(const float4*)(base + CC + j);
        split2(k.x * c0 - k.y * s0, k.x * s0 + k.y * c0, hi0, lo0);
        split2(k.z * c1 - k.w * s1, k.z * s1 + k.w * c1, hi1, lo1);
        *(uint2*)(g_Kh + orow + j) = make_uint2(hi0, hi1);
        *(uint2*)(g_Kl + orow + j) = make_uint2(lo0, lo1);

        float4 v = *(const float4*)(base + 2 * CC + j);
        split2(v.x, v.y, hi0, lo0);
        split2(v.z, v.w, hi1, lo1);
        *(uint2*)(g_Vh + orow + j) = make_uint2(hi0, hi1);
        *(uint2*)(g_Vl + orow + j) = make_uint2(lo0, lo1);
    }
}

// ---------------------------------------------------------------------------
// GEMM (round-7 proven config): CTA 128x128, K-chunk 32, 8 warps (64x32),
// cp.async(.ca) double-buffered, 2 CTAs/SM.
// ---------------------------------------------------------------------------
#define SPAD 40
#define G_ARR (128 * SPAD * 2)      // 10240 B per array
#define G_STAGE (4 * G_ARR)         // 40960 B per stage

__global__ __launch_bounds__(256, 2) void gemm_b16(
        const __nv_bfloat16* __restrict__ Ahg, const __nv_bfloat16* __restrict__ Alg,
        const __nv_bfloat16* __restrict__ Whg, const __nv_bfloat16* __restrict__ Wlg,
        const float* __restrict__ bias, float* __restrict__ Cm,
        int M, int Nc, int K) {
    extern __shared__ __align__(16) char sm[];
    const uint32_t sbase = smem_u32(sm);

    const int tid = threadIdx.x;
    const int wid = tid >> 5;
    const int lane = tid & 31;
    const int m0 = blockIdx.y * 128;
    const int n0 = blockIdx.x * 128;
    const int wm = (wid >> 2) * 64;
    const int wn = (wid & 3) * 32;

    const int lrow = tid >> 1;
    const int lcol = (tid & 1) * 16;
    const __nv_bfloat16* Ahp = Ahg + (size_t)(m0 + lrow) * K + lcol;
    const __nv_bfloat16* Alp = Alg + (size_t)(m0 + lrow) * K + lcol;
    const __nv_bfloat16* Whp = Whg + (size_t)(n0 + lrow) * K + lcol;
    const __nv_bfloat16* Wlp = Wlg + (size_t)(n0 + lrow) * K + lcol;
    const uint32_t ldst = sbase + (lrow * SPAD + lcol) * 2;

    float acc[4][4][4];
#pragma unroll
    for (int i = 0; i < 4; i++)
#pragma unroll
        for (int j = 0; j < 4; j++)
#pragma unroll
            for (int f = 0; f < 4; f++) acc[i][j][f] = 0.f;

    const uint32_t a_row = wm + (lane & 15);
    const uint32_t a_coff = (lane >> 4) * 8;
    const uint32_t b_row = wn + ((lane >> 4) << 3) + (lane & 7);
    const uint32_t b_coff = ((lane >> 3) & 1) * 8;

    {
        uint32_t d = ldst;
        cp16(d, Ahp); cp16(d + 16, Ahp + 8);
        cp16(d + G_ARR, Alp); cp16(d + G_ARR + 16, Alp + 8);
        cp16(d + 2 * G_ARR, Whp); cp16(d + 2 * G_ARR + 16, Whp + 8);
        cp16(d + 3 * G_ARR, Wlp); cp16(d + 3 * G_ARR + 16, Wlp + 8);
    }
    cp_commit();

    int buf = 0;
    for (int k0 = 0; k0 < K; k0 += 32) {
        if (k0 + 32 < K) {
            uint32_t d = ldst + (buf ^ 1) * G_STAGE;
            int kn = k0 + 32;
            cp16(d, Ahp + kn); cp16(d + 16, Ahp + kn + 8);
            cp16(d + G_ARR, Alp + kn); cp16(d + G_ARR + 16, Alp + kn + 8);
            cp16(d + 2 * G_ARR, Whp + kn); cp16(d + 2 * G_ARR + 16, Whp + kn + 8);
            cp16(d + 3 * G_ARR, Wlp + kn); cp16(d + 3 * G_ARR + 16, Wlp + kn + 8);
        }
        cp_commit();
        cp_wait1();
        __syncthreads();

        const uint32_t sAh = sbase + buf * G_STAGE;
        const uint32_t sAl = sAh + G_ARR;
        const uint32_t sBh = sAh + 2 * G_ARR;
        const uint32_t sBl = sAh + 3 * G_ARR;

#pragma unroll
        for (int ks = 0; ks < 2; ks++) {
            const uint32_t kc = ks * 16;
            uint32_t afh[4][4], afl[4][4];
#pragma unroll
            for (int mt = 0; mt < 4; mt++) {
                uint32_t off = ((a_row + mt * 16) * SPAD + kc + a_coff) * 2;
                ldmx4(afh[mt], sAh + off);
                ldmx4(afl[mt], sAl + off);
            }
            uint32_t bfh[2][4], bfl[2][4];
#pragma unroll
            for (int bt = 0; bt < 2; bt++) {
                uint32_t off = ((b_row + bt * 16) * SPAD + kc + b_coff) * 2;
                ldmx4(bfh[bt], sBh + off);
                ldmx4(bfl[bt], sBl + off);
            }
#pragma unroll
            for (int mt = 0; mt < 4; mt++)
#pragma unroll
                for (int nt = 0; nt < 4; nt++) {
                    uint32_t* bh = &bfh[nt >> 1][(nt & 1) * 2];
                    uint32_t* bl = &bfl[nt >> 1][(nt & 1) * 2];
                    mma_bf16(acc[mt][nt], afh[mt], bh);
                    mma_bf16(acc[mt][nt], afh[mt], bl);
                    mma_bf16(acc[mt][nt], afl[mt], bh);
                }
        }
        __syncthreads();
        buf ^= 1;
    }

    const int erow = lane >> 2;
    const int ecol = (lane & 3) * 2;
#pragma unroll
    for (int mt = 0; mt < 4; mt++) {
#pragma unroll
        for (int nt = 0; nt < 4; nt++) {
            int gr = m0 + wm + mt * 16 + erow;
            int gc = n0 + wn + nt * 8 + ecol;
            float b0 = 0.f, b1 = 0.f;
            if (bias) { b0 = bias[gc]; b1 = bias[gc + 1]; }
            *(float2*)(Cm + (size_t)gr * Nc + gc) =
                make_float2(acc[mt][nt][0] + b0, acc[mt][nt][1] + b1);
            *(float2*)(Cm + (size_t)(gr + 8) * Nc + gc) =
                make_float2(acc[mt][nt][2] + b0, acc[mt][nt][3] + b1);
        }
    }
}

// ---------------------------------------------------------------------------
// Flash attention (round-7 config; exp2-domain softmax, deferred l-reduce):
// 128 q-rows, 256 threads, 8 warps, cp.async(.ca) double-buffered K/V.
// ---------------------------------------------------------------------------
#define APAD 72
#define A_QARR (128 * APAD * 2)       // 18432 B (Qh or Ql)
#define A_KARR (64 * APAD * 2)        // 9216 B per KV array
#define A_KSTAGE (4 * A_KARR)         // 36864 B per stage
#define A_KBASE (2 * A_QARR)          // 36864

__global__ __launch_bounds__(256, 1) void attn_mma(void) {
    extern __shared__ __align__(16) char sm[];
    const uint32_t sbase = smem_u32(sm);

    const int t = threadIdx.x;
    const int wid = t >> 5;
    const int lane = t & 31;
    const int h = blockIdx.y;
    const int b = blockIdx.z;
    const int q0 = blockIdx.x * 128;

    const size_t hbase = (size_t)(b * HH + h) * NN * 64;

    const int krow = t >> 2, kc16 = (t & 3) * 16;
    const uint32_t kdst = sbase + A_KBASE + (krow * APAD + kc16) * 2;
    const size_t ksrc0 = hbase + (size_t)krow * 64 + kc16;

    {
        uint32_t d = kdst;
        cp16(d, g_Kh + ksrc0); cp16(d + 16, g_Kh + ksrc0 + 8);
        cp16(d + A_KARR, g_Kl + ksrc0); cp16(d + A_KARR + 16, g_Kl + ksrc0 + 8);
        cp16(d + 2 * A_KARR, g_Vh + ksrc0); cp16(d + 2 * A_KARR + 16, g_Vh + ksrc0 + 8);
        cp16(d + 3 * A_KARR, g_Vl + ksrc0); cp16(d + 3 * A_KARR + 16, g_Vl + ksrc0 + 8);
    }
    cp_commit();

    __nv_bfloat16* const Qh = (__nv_bfloat16*)sm;
    __nv_bfloat16* const Ql = Qh + 128 * APAD;
    {
        int row = t >> 1, half = (t & 1) * 32;
        size_t src = hbase + (size_t)(q0 + row) * 64 + half;
        size_t dst = (size_t)row * APAD + half;
#pragma unroll
        for (int j = 0; j < 32; j += 8) {
            *(uint4*)(Qh + dst + j) = *(const uint4*)(g_Qh + src + j);
            *(uint4*)(Ql + dst + j) = *(const uint4*)(g_Ql + src + j);
        }
    }
    __syncthreads();

    uint32_t qfh[4][4], qfl[4][4];
    {
        const uint32_t arow = wid * 16 + (lane & 15);
        const uint32_t acoff = (lane >> 4) * 8;
#pragma unroll
        for (int ks = 0; ks < 4; ks++) {
            uint32_t off = (arow * APAD + ks * 16 + acoff) * 2;
            ldmx4(qfh[ks], sbase + off);
            ldmx4(qfl[ks], sbase + A_QARR + off);
        }
    }

    float o[8][4];
#pragma unroll
    for (int i = 0; i < 8; i++)
#pragma unroll
        for (int f = 0; f < 4; f++) o[i][f] = 0.f;
    float m0 = -1e30f, m1 = -1e30f, l0 = 0.f, l1 = 0.f;   // l lane-partial

    const uint32_t b_row = ((lane >> 4) << 3) + (lane & 7);
    const uint32_t b_coff = ((lane >> 3) & 1) * 8;
    const uint32_t v_row = ((lane >> 3) & 1) * 8 + (lane & 7);
    const uint32_t v_coff = (lane >> 4) * 8;

    int buf = 0;
    for (int kt = 0; kt < NN / 64; kt++) {
        if (kt + 1 < NN / 64) {
            uint32_t d = kdst + (buf ^ 1) * A_KSTAGE;
            size_t src = ksrc0 + (size_t)(kt + 1) * 64 * 64;
            cp16(d, g_Kh + src); cp16(d + 16, g_Kh + src + 8);
            cp16(d + A_KARR, g_Kl + src); cp16(d + A_KARR + 16, g_Kl + src + 8);
            cp16(d + 2 * A_KARR, g_Vh + src); cp16(d + 2 * A_KARR + 16, g_Vh + src + 8);
            cp16(d + 3 * A_KARR, g_Vl + src); cp16(d + 3 * A_KARR + 16, g_Vl + src + 8);
        }
        cp_commit();
        cp_wait1();
        __syncthreads();

        const uint32_t sKh = sbase + A_KBASE + buf * A_KSTAGE;
        const uint32_t sKl = sKh + A_KARR;
        const uint32_t sVh = sKh + 2 * A_KARR;
        const uint32_t sVl = sKh + 3 * A_KARR;

        // ---- S = Q.K^T (S is in log2 units: Q pre-scaled by scale*log2e) ----
        float s[8][4];
#pragma unroll
        for (int i = 0; i < 8; i++)
#pragma unroll
            for (int f = 0; f < 4; f++) s[i][f] = 0.f;
#pragma unroll
        for (int ks = 0; ks < 4; ks++) {
            const uint32_t kc = ks * 16;
#pragma unroll
            for (int g = 0; g < 4; g++) {
                uint32_t bh[4], bl[4];
                uint32_t off = ((g * 16 + b_row) * APAD + kc + b_coff) * 2;
                ldmx4(bh, sKh + off);
                ldmx4(bl, sKl + off);
                mma_bf16(s[2 * g],     qfh[ks], &bh[0]);
                mma_bf16(s[2 * g],     qfh[ks], &bl[0]);
                mma_bf16(s[2 * g],     qfl[ks], &bh[0]);
                mma_bf16(s[2 * g + 1], qfh[ks], &bh[2]);
                mma_bf16(s[2 * g + 1], qfh[ks], &bl[2]);
                mma_bf16(s[2 * g + 1], qfl[ks], &bh[2]);
            }
        }

        // ---- online softmax (exp2 domain; l kept lane-partial) ----
        float tm0 = -1e30f, tm1 = -1e30f;
#pragma unroll
        for (int nt = 0; nt < 8; nt++) {
            tm0 = fmaxf(tm0, fmaxf(s[nt][0], s[nt][1]));
            tm1 = fmaxf(tm1, fmaxf(s[nt][2], s[nt][3]));
        }
        tm0 = fmaxf(tm0, __shfl_xor_sync(0xffffffffu, tm0, 1));
        tm0 = fmaxf(tm0, __shfl_xor_sync(0xffffffffu, tm0, 2));
        tm1 = fmaxf(tm1, __shfl_xor_sync(0xffffffffu, tm1, 1));
        tm1 = fmaxf(tm1, __shfl_xor_sync(0xffffffffu, tm1, 2));
        float mn0 = fmaxf(m0, tm0), mn1 = fmaxf(m1, tm1);
        float al0 = exp2f(m0 - mn0), al1 = exp2f(m1 - mn1);
        m0 = mn0; m1 = mn1;
        float rs0 = 0.f, rs1 = 0.f;
#pragma unroll
        for (int nt = 0; nt < 8; nt++) {
            s[nt][0] = exp2f(s[nt][0] - m0);
            s[nt][1] = exp2f(s[nt][1] - m0);
            s[nt][2] = exp2f(s[nt][2] - m1);
            s[nt][3] = exp2f(s[nt][3] - m1);
            rs0 += s[nt][0] + s[nt][1];
            rs1 += s[nt][2] + s[nt][3];
        }
        l0 = l0 * al0 + rs0;        // lane-partial; reduced once at epilogue
        l1 = l1 * al1 + rs1;
#pragma unroll
        for (int nt = 0; nt < 8; nt++) {
            o[nt][0] *= al0; o[nt][1] *= al0;
            o[nt][2] *= al1; o[nt][3] *= al1;
        }

        // ---- pack P hi/lo from registers ----
        uint32_t ph[4][4], pl[4][4];
#pragma unroll
        for (int ks = 0; ks < 4; ks++) {
#pragma unroll
            for (int hf = 0; hf < 2; hf++) {
                int nt = 2 * ks + hf;
                split2(s[nt][0], s[nt][1], ph[ks][hf * 2 + 0], pl[ks][hf * 2 + 0]);
                split2(s[nt][2], s[nt][3], ph[ks][hf * 2 + 1], pl[ks][hf * 2 + 1]);
            }
        }

        // ---- O += P.V ----
#pragma unroll
        for (int ks = 0; ks < 4; ks++) {
            const uint32_t kr = ks * 16 + v_row;
#pragma unroll
            for (int g = 0; g < 4; g++) {
                uint32_t vh4[4], vl4[4];
                uint32_t off = (kr * APAD + g * 16 + v_coff) * 2;
                ldmx4t(vh4, sVh + off);
                ldmx4t(vl4, sVl + off);
                mma_bf16(o[2 * g],     ph[ks], &vh4[0]);
                mma_bf16(o[2 * g],     ph[ks], &vl4[0]);
                mma_bf16(o[2 * g],     pl[ks], &vh4[0]);
                mma_bf16(o[2 * g + 1], ph[ks], &vh4[2]);
                mma_bf16(o[2 * g + 1], ph[ks], &vl4[2]);
                mma_bf16(o[2 * g + 1], pl[ks], &vh4[2]);
            }
        }
        __syncthreads();
        buf ^= 1;
    }

    // ---- epilogue: reduce l across the 4-lane row group, write pre-split ----
    l0 += __shfl_xor_sync(0xffffffffu, l0, 1);
    l0 += __shfl_xor_sync(0xffffffffu, l0, 2);
    l1 += __shfl_xor_sync(0xffffffffu, l1, 1);
    l1 += __shfl_xor_sync(0xffffffffu, l1, 2);
    float inv0 = 1.f / l0, inv1 = 1.f / l1;
    int r0 = q0 + wid * 16 + (lane >> 2);
    int cbase = (lane & 3) * 2;
    size_t base0 = (size_t)(b * NN + r0) * CC + h * DD + cbase;
    size_t base1 = base0 + (size_t)8 * CC;
#pragma unroll
    for (int nt = 0; nt < 8; nt++) {
        uint32_t hi, lo;
        split2(o[nt][0] * inv0, o[nt][1] * inv0, hi, lo);
        *(uint32_t*)(g_ah + base0 + nt * 8) = hi;
        *(uint32_t*)(g_al + base0 + nt * 8) = lo;
        split2(o[nt][2] * inv1, o[nt][3] * inv1, hi, lo);
        *(uint32_t*)(g_ah + base1 + nt * 8) = hi;
        *(uint32_t*)(g_al + base1 + nt * 8) = lo;
    }
}

// ---------------------------------------------------------------------------
extern "C" void kernel_launch(void* const* d_in, const int* in_sizes, int n_in,
                              void* d_out, int out_size) {
    const float* x      = (const float*)d_in[0];
    const float* freqs  = (const float*)d_in[1];
    const float* w_qkv  = (const float*)d_in[2];
    const float* w_proj = (const float*)d_in[3];
    const float* b_proj = (const float*)d_in[4];
    float* out = (float*)d_out;

    float* qkv;
    cudaGetSymbolAddress((void**)&qkv, g_qkv);
    __nv_bfloat16 *xh, *xl, *wqh, *wql, *wph, *wpl, *ah, *al;
    cudaGetSymbolAddress((void**)&xh, g_xh);
    cudaGetSymbolAddress((void**)&xl, g_xl);
    cudaGetSymbolAddress((void**)&wqh, g_wqh);
    cudaGetSymbolAddress((void**)&wql, g_wql);
    cudaGetSymbolAddress((void**)&wph, g_wph);
    cudaGetSymbolAddress((void**)&wpl, g_wpl);
    cudaGetSymbolAddress((void**)&ah, g_ah);
    cudaGetSymbolAddress((void**)&al, g_al);

    static int smem_set = 0;
    if (!smem_set) {
        cudaFuncSetAttribute(gemm_b16, cudaFuncAttributeMaxDynamicSharedMemorySize,
                             2 * G_STAGE);
        cudaFuncSetAttribute(attn_mma, cudaFuncAttributeMaxDynamicSharedMemorySize,
                             A_KBASE + 2 * A_KSTAGE);
        smem_set = 1;
    }

    // 0) pre-split inputs
    split_kernel<<<(MR * CC / 4 + 255) / 256, 256>>>(x, xh, xl, MR * CC / 4);
    split_kernel<<<(3 * CC * CC / 4 + 255) / 256, 256>>>(w_qkv, wqh, wql, 3 * CC * CC / 4);
    split_kernel<<<(CC * CC / 4 + 255) / 256, 256>>>(w_proj, wph, wpl, CC * CC / 4);

    // 1) qkv = x @ w_qkv^T
    gemm_b16<<<dim3(3 * CC / 128, MR / 128), 256, 2 * G_STAGE>>>(
        xh, xl, wqh, wql, nullptr, qkv, MR, 3 * CC, CC);
    // 2) RoPE + split q/k/v (head-contiguous; q pre-scaled for exp2 domain)
    prep_qkv<<<(BB * NN * HH * 2) / 256, 256>>>(qkv, freqs);
    // 3) attention (outputs pre-split g_ah/g_al)
    attn_mma<<<dim3(NN / 128, HH, BB), 256, A_KBASE + 2 * A_KSTAGE>>>();
    // 4) out = attn @ w_proj^T + b_proj
    gemm_b16<<<dim3(CC / 128, MR / 128), 256, 2 * G_STAGE>>>(
        ah, al, wph, wpl, b_proj, out, MR, CC, CC);
}